// round 13
// baseline (speedup 1.0000x reference)
#include <cuda_runtime.h>
#include <cstdint>
#include <cstddef>

// ---------------------------------------------------------------------------
// Problem constants
// ---------------------------------------------------------------------------
#define BDIM 512
constexpr int B_ = 64;    // batch
constexpr int T_ = 96;    // seq len
constexpr int P_ = 256;   // points
constexpr int H_ = 128;   // hidden
constexpr int G_ = 512;   // 4*H gates
constexpr int O_ = 24;    // pred_len
constexpr int KC = 16;            // k-rows per streamed chunk
constexpr int NCH = H_ / KC;      // 8 chunks per timestep

// 128 MB scratch: W_hh transposed to [p][k][g] with each weight duplicated
// into an f32x2 pair (w,w) so the packed-FMA inner loop needs no reg packing.
__device__ float g_wt[(size_t)P_ * H_ * G_ * 2];

// ---------------------------------------------------------------------------
// PTX helpers
// ---------------------------------------------------------------------------
__device__ __forceinline__ unsigned long long fma2(unsigned long long a,
                                                   unsigned long long b,
                                                   unsigned long long c) {
    unsigned long long d;
    asm("fma.rn.f32x2 %0, %1, %2, %3;" : "=l"(d) : "l"(a), "l"(b), "l"(c));
    return d;
}
__device__ __forceinline__ void lds_v2u64(unsigned addr, unsigned long long& a,
                                          unsigned long long& b) {
    asm volatile("ld.shared.v2.u64 {%0, %1}, [%2];" : "=l"(a), "=l"(b) : "r"(addr));
}
__device__ __forceinline__ unsigned long long lds_u64(unsigned addr) {
    unsigned long long a;
    asm volatile("ld.shared.u64 %0, [%1];" : "=l"(a) : "r"(addr));
    return a;
}
__device__ __forceinline__ void cp16(unsigned dst, const void* src) {
    asm volatile("cp.async.cg.shared.global [%0], [%1], 16;"
                 :: "r"(dst), "l"(src) : "memory");
}
__device__ __forceinline__ void cp_commit() {
    asm volatile("cp.async.commit_group;" ::: "memory");
}
__device__ __forceinline__ void cp_wait1() {
    asm volatile("cp.async.wait_group 1;" ::: "memory");
}
__device__ __forceinline__ float fsig(float x) {
    // 1/(1+e^-x) via MUFU ex2 + rcp (errors ~1e-6, far under tolerance)
    float e;
    asm("ex2.approx.f32 %0, %1;" : "=f"(e) : "f"(x * -1.4426950408889634f));
    float r;
    asm("rcp.approx.f32 %0, %1;" : "=f"(r) : "f"(1.0f + e));
    return r;
}
__device__ __forceinline__ float ftanh(float x) {
    return fmaf(2.0f, fsig(2.0f * x), -1.0f);
}
__device__ __forceinline__ float2 unpk(unsigned long long v) {
    float2 r;
    asm("mov.b64 {%0, %1}, %2;" : "=f"(r.x), "=f"(r.y) : "l"(v));
    return r;
}

// ---------------------------------------------------------------------------
// Prep kernel: g_wt[p][k][g] (duplicated pairs) = W_hh[p][g][k]
// One thread per (p,k,g); writes are fully coalesced float2.
// ---------------------------------------------------------------------------
__global__ void k_transpose(const float* __restrict__ whh) {
    unsigned idx = blockIdx.x * BDIM + threadIdx.x;  // exact grid: P*H*G threads
    unsigned g  = idx & (G_ - 1);
    unsigned pk = idx >> 9;
    unsigned k  = pk & (H_ - 1);
    unsigned p  = pk >> 7;
    float w = __ldg(&whh[((size_t)p * G_ + g) * H_ + k]);
    reinterpret_cast<float2*>(g_wt)[idx] = make_float2(w, w);
}

// ---------------------------------------------------------------------------
// Main kernel: one CTA per point.
// Thread layout: tid = tg*8 + tb; tg in [0,64) covers hidden pairs (2tg, 2tg+1)
// across all 4 gate classes; tb in [0,8) covers 8 batches (4 b-pairs).
// Per thread: acc[4 gates][2 h][4 b-pairs] as f32x2; c state in registers.
// W streamed L2 -> smem via cp.async double buffer (64KB chunks, wraps mod 8).
// ---------------------------------------------------------------------------
__global__ void __launch_bounds__(BDIM, 1) k_lstm(
    const float* __restrict__ x,
    const float* __restrict__ wih,
    const float* __restrict__ bih,
    const float* __restrict__ bhh,
    const float* __restrict__ wfc,
    const float* __restrict__ bfc,
    float* __restrict__ out)
{
    extern __shared__ float sm[];
    // float offsets:
    //   h_s   [128][64]        : 0     .. 8191
    //   x_s   [96][64]         : 8192  .. 14335
    //   wih_d [512][2] (dup)   : 14336 .. 15359
    //   bs_d  [512][2] (dup)   : 15360 .. 16383
    //   wbuf  [2][16][1024]    : 16384 .. 49151     (2 x 64KB)
    float* h_s   = sm;
    float* x_s   = sm + 8192;
    float* wih_d = sm + 14336;
    float* bs_d  = sm + 15360;

    const int p   = blockIdx.x;
    const int tid = threadIdx.x;
    const int tg  = tid >> 3;   // 0..63
    const int tb  = tid & 7;    // 0..7

    // --- init smem -------------------------------------------------------
    for (int i = tid; i < H_ * B_; i += BDIM) h_s[i] = 0.0f;       // h0 = 0
    for (int i = tid; i < T_ * B_; i += BDIM) {
        int t = i >> 6, b = i & 63;
        x_s[i] = x[((size_t)b * T_ + t) * P_ + p];                 // x[b,t,p,0]
    }
    if (tid < G_) {
        float w = wih[(size_t)p * G_ + tid];                       // W_ih[p,g,0]
        wih_d[2 * tid] = w;  wih_d[2 * tid + 1] = w;
        float bs = bih[(size_t)p * G_ + tid] + bhh[(size_t)p * G_ + tid];
        bs_d[2 * tid] = bs;  bs_d[2 * tid + 1] = bs;
    }

    const unsigned sbase    = (unsigned)__cvta_generic_to_shared(sm);
    const unsigned h_base   = sbase;
    const unsigned x_base   = sbase + 8192u * 4u;
    const unsigned wih_base = sbase + 14336u * 4u;
    const unsigned bs_base  = sbase + 15360u * 4u;
    const unsigned wb_base  = sbase + 16384u * 4u;

    const float* wsrc = g_wt + (size_t)p * (H_ * G_ * 2);  // 131072 floats

    // --- prologue: prefetch chunk0 -> buf0, chunk1 -> buf1 ---------------
    {
        const char* s0 = (const char*)wsrc;
        const char* s1 = (const char*)(wsrc + KC * 1024);
#pragma unroll
        for (int n = 0; n < 8; ++n)
            cp16(wb_base + (unsigned)(tid + n * BDIM) * 16u, s0 + (size_t)(tid + n * BDIM) * 16);
        cp_commit();
#pragma unroll
        for (int n = 0; n < 8; ++n)
            cp16(wb_base + 65536u + (unsigned)(tid + n * BDIM) * 16u, s1 + (size_t)(tid + n * BDIM) * 16);
        cp_commit();
    }
    __syncthreads();   // h_s / x_s / wih_d / bs_d visible

    float2 cst[2][4];
#pragma unroll
    for (int hh = 0; hh < 2; ++hh)
#pragma unroll
        for (int j = 0; j < 4; ++j) cst[hh][j] = make_float2(0.0f, 0.0f);

    // --- time loop --------------------------------------------------------
    for (int t = 0; t < T_; ++t) {
        // acc init: gate = x[b]*W_ih[g] + (b_ih+b_hh)[g]
        unsigned long long acc[4][2][4];
        unsigned long long xp[4];
#pragma unroll
        for (int j = 0; j < 4; ++j)
            xp[j] = lds_u64(x_base + (unsigned)(t * 64 + tb * 8 + 2 * j) * 4u);
#pragma unroll
        for (int c = 0; c < 4; ++c) {
#pragma unroll
            for (int hh = 0; hh < 2; ++hh) {
                int g = c * 128 + 2 * tg + hh;
                unsigned long long wd = lds_u64(wih_base + (unsigned)g * 8u);
                unsigned long long bd = lds_u64(bs_base + (unsigned)g * 8u);
#pragma unroll
                for (int j = 0; j < 4; ++j) acc[c][hh][j] = fma2(xp[j], wd, bd);
            }
        }

        // k loop: gates += h @ W_hh^T, streamed in 8 chunks of 16 k's
        for (int ch = 0; ch < NCH; ++ch) {
            cp_wait1();          // chunk `ch` resident in buf[ch&1]
            __syncthreads();     // visibility of cp.async data + h_s from epilogue

            const unsigned bufb = wb_base + (unsigned)(ch & 1) * 65536u;
            const unsigned hb   = h_base + (unsigned)(ch * KC * 64 + tb * 8) * 4u;
#pragma unroll
            for (int kk = 0; kk < KC; ++kk) {
                unsigned long long hp0, hp1, hp2, hp3;
                lds_v2u64(hb + (unsigned)kk * 256u, hp0, hp1);
                lds_v2u64(hb + (unsigned)kk * 256u + 16u, hp2, hp3);
#pragma unroll
                for (int c = 0; c < 4; ++c) {
                    unsigned long long w0, w1;
                    lds_v2u64(bufb + (unsigned)(kk * 4096 + c * 1024 + tg * 16), w0, w1);
                    acc[c][0][0] = fma2(hp0, w0, acc[c][0][0]);
                    acc[c][0][1] = fma2(hp1, w0, acc[c][0][1]);
                    acc[c][0][2] = fma2(hp2, w0, acc[c][0][2]);
                    acc[c][0][3] = fma2(hp3, w0, acc[c][0][3]);
                    acc[c][1][0] = fma2(hp0, w1, acc[c][1][0]);
                    acc[c][1][1] = fma2(hp1, w1, acc[c][1][1]);
                    acc[c][1][2] = fma2(hp2, w1, acc[c][1][2]);
                    acc[c][1][3] = fma2(hp3, w1, acc[c][1][3]);
                }
            }
            __syncthreads();     // everyone done reading buf[ch&1]

            // prefetch chunk (ch+2) % 8 into buf[ch&1] (wraps across timesteps)
            int nc = (ch + 2) & 7;
            const char* src = (const char*)(wsrc + (size_t)nc * KC * 1024);
            unsigned dst = wb_base + (unsigned)(ch & 1) * 65536u;
#pragma unroll
            for (int n = 0; n < 8; ++n)
                cp16(dst + (unsigned)(tid + n * BDIM) * 16u, src + (size_t)(tid + n * BDIM) * 16);
            cp_commit();
        }

        // epilogue: torch gate order i,f,g,o; c = f*c + i*tanh(g); h = o*tanh(c)
#pragma unroll
        for (int hh = 0; hh < 2; ++hh) {
            int hrow = 2 * tg + hh;
#pragma unroll
            for (int j = 0; j < 4; ++j) {
                float2 iv = unpk(acc[0][hh][j]);
                float2 fv = unpk(acc[1][hh][j]);
                float2 gv = unpk(acc[2][hh][j]);
                float2 ov = unpk(acc[3][hh][j]);
                float c0 = fsig(fv.x) * cst[hh][j].x + fsig(iv.x) * ftanh(gv.x);
                float c1 = fsig(fv.y) * cst[hh][j].y + fsig(iv.y) * ftanh(gv.y);
                cst[hh][j] = make_float2(c0, c1);
                float h0 = fsig(ov.x) * ftanh(c0);
                float h1 = fsig(ov.y) * ftanh(c1);
                *reinterpret_cast<float2*>(&h_s[hrow * 64 + tb * 8 + 2 * j]) =
                    make_float2(h0, h1);
            }
        }
        // next iteration's cp_wait1 + __syncthreads orders these h_s writes
        // before any thread's chunk-0 compute.
    }
    __syncthreads();   // final h_s visible to all for the FC

    // --- final FC: out[b, o, p] = h[b,:] . W_fc[p,o,:] + b_fc[p,o] -------
#pragma unroll
    for (int r = 0; r < 3; ++r) {
        int idx = tid + r * BDIM;       // 0..1535 == 64*24
        int b = idx / 24;
        int o = idx - b * 24;
        const float4* wf = reinterpret_cast<const float4*>(wfc + ((size_t)p * O_ + o) * H_);
        float acc = bfc[(size_t)p * O_ + o];
#pragma unroll
        for (int k4 = 0; k4 < 32; ++k4) {
            float4 w = wf[k4];
            int k = k4 * 4;
            acc += h_s[k * 64 + b] * w.x;
            acc += h_s[(k + 1) * 64 + b] * w.y;
            acc += h_s[(k + 2) * 64 + b] * w.z;
            acc += h_s[(k + 3) * 64 + b] * w.w;
        }
        out[((size_t)b * O_ + o) * P_ + p] = acc;
    }
}

// ---------------------------------------------------------------------------
// Launch
// ---------------------------------------------------------------------------
extern "C" void kernel_launch(void* const* d_in, const int* in_sizes, int n_in,
                              void* d_out, int out_size) {
    (void)in_sizes; (void)n_in; (void)out_size;
    const float* x   = (const float*)d_in[0];  // [B,T,P,1]
    const float* wih = (const float*)d_in[1];  // [P,4H,1]
    const float* whh = (const float*)d_in[2];  // [P,4H,H]
    const float* bih = (const float*)d_in[3];  // [P,4H]
    const float* bhh = (const float*)d_in[4];  // [P,4H]
    const float* wfc = (const float*)d_in[5];  // [P,O,H]
    const float* bfc = (const float*)d_in[6];  // [P,O]
    float* out = (float*)d_out;                // [B,O,P]

    cudaFuncSetAttribute(k_lstm, cudaFuncAttributeMaxDynamicSharedMemorySize, 196608);

    // transpose+duplicate W_hh (exact grid: P*H*G threads)
    k_transpose<<<(P_ * H_ * G_) / BDIM, BDIM>>>(whh);
    // one CTA per point
    k_lstm<<<P_, BDIM, 196608>>>(x, wih, bih, bhh, wfc, bfc, out);
}

// round 14
// speedup vs baseline: 1.1718x; 1.1718x over previous
#include <cuda_runtime.h>
#include <cstdint>
#include <cstddef>

// ---------------------------------------------------------------------------
// Problem constants
// ---------------------------------------------------------------------------
#define TDIM 512            // transpose kernel block
#define BDIM 256            // lstm kernel block (8 warps)
constexpr int B_ = 64;    // batch
constexpr int T_ = 96;    // seq len
constexpr int P_ = 256;   // points
constexpr int H_ = 128;   // hidden
constexpr int G_ = 512;   // 4*H gates
constexpr int O_ = 24;    // pred_len
constexpr int KC = 16;            // k-rows per streamed chunk
constexpr int NCH = H_ / KC;      // 8 chunks per timestep

// 128 MB scratch: W_hh transposed to [p][k][g] with each weight duplicated
// into an f32x2 pair (w,w) so the packed-FMA inner loop needs no reg packing.
__device__ float g_wt[(size_t)P_ * H_ * G_ * 2];

// ---------------------------------------------------------------------------
// PTX helpers
// ---------------------------------------------------------------------------
__device__ __forceinline__ unsigned long long fma2(unsigned long long a,
                                                   unsigned long long b,
                                                   unsigned long long c) {
    unsigned long long d;
    asm("fma.rn.f32x2 %0, %1, %2, %3;" : "=l"(d) : "l"(a), "l"(b), "l"(c));
    return d;
}
__device__ __forceinline__ void lds_v2u64(unsigned addr, unsigned long long& a,
                                          unsigned long long& b) {
    asm volatile("ld.shared.v2.u64 {%0, %1}, [%2];" : "=l"(a), "=l"(b) : "r"(addr));
}
__device__ __forceinline__ unsigned long long lds_u64(unsigned addr) {
    unsigned long long a;
    asm volatile("ld.shared.u64 %0, [%1];" : "=l"(a) : "r"(addr));
    return a;
}
__device__ __forceinline__ void cp16(unsigned dst, const void* src) {
    asm volatile("cp.async.cg.shared.global [%0], [%1], 16;"
                 :: "r"(dst), "l"(src) : "memory");
}
__device__ __forceinline__ void cp_commit() {
    asm volatile("cp.async.commit_group;" ::: "memory");
}
__device__ __forceinline__ void cp_wait1() {
    asm volatile("cp.async.wait_group 1;" ::: "memory");
}
__device__ __forceinline__ float ftanh(float x) {
    float y;
    asm("tanh.approx.f32 %0, %1;" : "=f"(y) : "f"(x));
    return y;
}
__device__ __forceinline__ float fsig(float x) {
    // sigmoid(x) = 0.5*tanh(0.5x) + 0.5  (single MUFU)
    return fmaf(0.5f, ftanh(0.5f * x), 0.5f);
}
__device__ __forceinline__ float2 unpk(unsigned long long v) {
    float2 r;
    asm("mov.b64 {%0, %1}, %2;" : "=f"(r.x), "=f"(r.y) : "l"(v));
    return r;
}

// ---------------------------------------------------------------------------
// Prep kernel: g_wt[p][k][g] (duplicated pairs) = W_hh[p][g][k]
// ---------------------------------------------------------------------------
__global__ void k_transpose(const float* __restrict__ whh) {
    unsigned idx = blockIdx.x * TDIM + threadIdx.x;  // exact grid: P*H*G threads
    unsigned g  = idx & (G_ - 1);
    unsigned pk = idx >> 9;
    unsigned k  = pk & (H_ - 1);
    unsigned p  = pk >> 7;
    float w = __ldg(&whh[((size_t)p * G_ + g) * H_ + k]);
    reinterpret_cast<float2*>(g_wt)[idx] = make_float2(w, w);
}

// ---------------------------------------------------------------------------
// Main kernel: one CTA per point, 256 threads.
// tid = tg*4 + tb; tg in [0,64) -> hidden units (2tg, 2tg+1) over all 4 gate
// classes; tb in [0,4) -> 16 batches (8 b-pairs) starting at tb*16.
// Per thread: acc[4 gates][2 units][8 b-pairs] as f32x2 (2.0 B/fma2 vs 3.0
// before); c state in registers. W streamed L2 -> smem via cp.async
// double buffer (64KB chunks, wraps mod 8).
// ---------------------------------------------------------------------------
__global__ void __launch_bounds__(BDIM, 1) k_lstm(
    const float* __restrict__ x,
    const float* __restrict__ wih,
    const float* __restrict__ bih,
    const float* __restrict__ bhh,
    const float* __restrict__ wfc,
    const float* __restrict__ bfc,
    float* __restrict__ out)
{
    extern __shared__ float sm[];
    // float offsets:
    //   h_s   [128][64]        : 0     .. 8191
    //   x_s   [96][64]         : 8192  .. 14335
    //   wih_d [512][2] (dup)   : 14336 .. 15359
    //   bs_d  [512][2] (dup)   : 15360 .. 16383
    //   wbuf  [2][16][1024]    : 16384 .. 49151     (2 x 64KB)
    float* h_s   = sm;
    float* x_s   = sm + 8192;
    float* wih_d = sm + 14336;
    float* bs_d  = sm + 15360;

    const int p   = blockIdx.x;
    const int tid = threadIdx.x;
    const int tg  = tid >> 2;   // 0..63
    const int tb  = tid & 3;    // 0..3

    // --- init smem -------------------------------------------------------
    for (int i = tid; i < H_ * B_; i += BDIM) h_s[i] = 0.0f;       // h0 = 0
    for (int i = tid; i < T_ * B_; i += BDIM) {
        int t = i >> 6, b = i & 63;
        x_s[i] = x[((size_t)b * T_ + t) * P_ + p];                 // x[b,t,p,0]
    }
    for (int i = tid; i < G_; i += BDIM) {
        float w = wih[(size_t)p * G_ + i];                         // W_ih[p,g,0]
        wih_d[2 * i] = w;  wih_d[2 * i + 1] = w;
        float bs = bih[(size_t)p * G_ + i] + bhh[(size_t)p * G_ + i];
        bs_d[2 * i] = bs;  bs_d[2 * i + 1] = bs;
    }

    const unsigned sbase    = (unsigned)__cvta_generic_to_shared(sm);
    const unsigned h_base   = sbase;
    const unsigned x_base   = sbase + 8192u * 4u;
    const unsigned wih_base = sbase + 14336u * 4u;
    const unsigned bs_base  = sbase + 15360u * 4u;
    const unsigned wb_base  = sbase + 16384u * 4u;

    const float* wsrc = g_wt + (size_t)p * (H_ * G_ * 2);  // 131072 floats

    // --- prologue: prefetch chunk0 -> buf0, chunk1 -> buf1 ---------------
    {
        const char* s0 = (const char*)wsrc;
        const char* s1 = (const char*)(wsrc + KC * 1024);
#pragma unroll
        for (int n = 0; n < 16; ++n)
            cp16(wb_base + (unsigned)(tid + n * BDIM) * 16u, s0 + (size_t)(tid + n * BDIM) * 16);
        cp_commit();
#pragma unroll
        for (int n = 0; n < 16; ++n)
            cp16(wb_base + 65536u + (unsigned)(tid + n * BDIM) * 16u, s1 + (size_t)(tid + n * BDIM) * 16);
        cp_commit();
    }
    __syncthreads();   // h_s / x_s / wih_d / bs_d visible

    float2 cst[2][8];
#pragma unroll
    for (int u = 0; u < 2; ++u)
#pragma unroll
        for (int j = 0; j < 8; ++j) cst[u][j] = make_float2(0.0f, 0.0f);

    // --- time loop --------------------------------------------------------
    for (int t = 0; t < T_; ++t) {
        // acc init: gate = x[b]*W_ih[g] + (b_ih+b_hh)[g]
        unsigned long long acc[4][2][8];
        unsigned long long xp[8];
#pragma unroll
        for (int j = 0; j < 4; ++j)
            lds_v2u64(x_base + (unsigned)(t * 64 + tb * 16 + 4 * j) * 4u,
                      xp[2 * j], xp[2 * j + 1]);
#pragma unroll
        for (int c = 0; c < 4; ++c) {
            unsigned long long wd0, wd1, bd0, bd1;
            lds_v2u64(wih_base + (unsigned)(c * 128 + 2 * tg) * 8u, wd0, wd1);
            lds_v2u64(bs_base + (unsigned)(c * 128 + 2 * tg) * 8u, bd0, bd1);
#pragma unroll
            for (int j = 0; j < 8; ++j) {
                acc[c][0][j] = fma2(xp[j], wd0, bd0);
                acc[c][1][j] = fma2(xp[j], wd1, bd1);
            }
        }

        // k loop: gates += h @ W_hh^T, streamed in 8 chunks of 16 k's
        for (int ch = 0; ch < NCH; ++ch) {
            cp_wait1();          // chunk `ch` resident in buf[ch&1]
            __syncthreads();     // visibility of cp.async data + h_s from epilogue

            const unsigned bufb = wb_base + (unsigned)(ch & 1) * 65536u;
            const unsigned hb   = h_base + (unsigned)(ch * KC * 64 + tb * 16) * 4u;
#pragma unroll
            for (int kk = 0; kk < KC; ++kk) {
                unsigned long long hp[8];
                lds_v2u64(hb + (unsigned)kk * 256u,       hp[0], hp[1]);
                lds_v2u64(hb + (unsigned)kk * 256u + 16u, hp[2], hp[3]);
                lds_v2u64(hb + (unsigned)kk * 256u + 32u, hp[4], hp[5]);
                lds_v2u64(hb + (unsigned)kk * 256u + 48u, hp[6], hp[7]);
#pragma unroll
                for (int c = 0; c < 4; ++c) {
                    unsigned long long w0, w1;
                    lds_v2u64(bufb + (unsigned)(kk * 4096 + c * 1024 + tg * 16), w0, w1);
                    acc[c][0][0] = fma2(hp[0], w0, acc[c][0][0]);
                    acc[c][0][1] = fma2(hp[1], w0, acc[c][0][1]);
                    acc[c][0][2] = fma2(hp[2], w0, acc[c][0][2]);
                    acc[c][0][3] = fma2(hp[3], w0, acc[c][0][3]);
                    acc[c][0][4] = fma2(hp[4], w0, acc[c][0][4]);
                    acc[c][0][5] = fma2(hp[5], w0, acc[c][0][5]);
                    acc[c][0][6] = fma2(hp[6], w0, acc[c][0][6]);
                    acc[c][0][7] = fma2(hp[7], w0, acc[c][0][7]);
                    acc[c][1][0] = fma2(hp[0], w1, acc[c][1][0]);
                    acc[c][1][1] = fma2(hp[1], w1, acc[c][1][1]);
                    acc[c][1][2] = fma2(hp[2], w1, acc[c][1][2]);
                    acc[c][1][3] = fma2(hp[3], w1, acc[c][1][3]);
                    acc[c][1][4] = fma2(hp[4], w1, acc[c][1][4]);
                    acc[c][1][5] = fma2(hp[5], w1, acc[c][1][5]);
                    acc[c][1][6] = fma2(hp[6], w1, acc[c][1][6]);
                    acc[c][1][7] = fma2(hp[7], w1, acc[c][1][7]);
                }
            }
            __syncthreads();     // everyone done reading buf[ch&1]

            // prefetch chunk (ch+2) % 8 into buf[ch&1] (wraps across timesteps)
            int nc = (ch + 2) & 7;
            const char* src = (const char*)(wsrc + (size_t)nc * KC * 1024);
            unsigned dst = wb_base + (unsigned)(ch & 1) * 65536u;
#pragma unroll
            for (int n = 0; n < 16; ++n)
                cp16(dst + (unsigned)(tid + n * BDIM) * 16u, src + (size_t)(tid + n * BDIM) * 16);
            cp_commit();
        }

        // epilogue: torch gate order i,f,g,o; c = f*c + i*tanh(g); h = o*tanh(c)
#pragma unroll
        for (int u = 0; u < 2; ++u) {
            int hrow = 2 * tg + u;
#pragma unroll
            for (int j = 0; j < 8; ++j) {
                float2 iv = unpk(acc[0][u][j]);
                float2 fv = unpk(acc[1][u][j]);
                float2 gv = unpk(acc[2][u][j]);
                float2 ov = unpk(acc[3][u][j]);
                float c0 = fsig(fv.x) * cst[u][j].x + fsig(iv.x) * ftanh(gv.x);
                float c1 = fsig(fv.y) * cst[u][j].y + fsig(iv.y) * ftanh(gv.y);
                cst[u][j] = make_float2(c0, c1);
                float h0 = fsig(ov.x) * ftanh(c0);
                float h1 = fsig(ov.y) * ftanh(c1);
                *reinterpret_cast<float2*>(&h_s[hrow * 64 + tb * 16 + 2 * j]) =
                    make_float2(h0, h1);
            }
        }
        // next iteration's cp_wait1 + __syncthreads orders these h_s writes
        // before any thread's chunk-0 compute.
    }
    __syncthreads();   // final h_s visible to all for the FC

    // --- final FC: out[b, o, p] = h[b,:] . W_fc[p,o,:] + b_fc[p,o] -------
#pragma unroll
    for (int r = 0; r < 6; ++r) {
        int idx = tid + r * BDIM;       // 0..1535 == 64*24
        int b = idx / 24;
        int o = idx - b * 24;
        const float4* wf = reinterpret_cast<const float4*>(wfc + ((size_t)p * O_ + o) * H_);
        float acc = bfc[(size_t)p * O_ + o];
#pragma unroll
        for (int k4 = 0; k4 < 32; ++k4) {
            float4 w = wf[k4];
            int k = k4 * 4;
            acc += h_s[k * 64 + b] * w.x;
            acc += h_s[(k + 1) * 64 + b] * w.y;
            acc += h_s[(k + 2) * 64 + b] * w.z;
            acc += h_s[(k + 3) * 64 + b] * w.w;
        }
        out[((size_t)b * O_ + o) * P_ + p] = acc;
    }
}

// ---------------------------------------------------------------------------
// Launch
// ---------------------------------------------------------------------------
extern "C" void kernel_launch(void* const* d_in, const int* in_sizes, int n_in,
                              void* d_out, int out_size) {
    (void)in_sizes; (void)n_in; (void)out_size;
    const float* x   = (const float*)d_in[0];  // [B,T,P,1]
    const float* wih = (const float*)d_in[1];  // [P,4H,1]
    const float* whh = (const float*)d_in[2];  // [P,4H,H]
    const float* bih = (const float*)d_in[3];  // [P,4H]
    const float* bhh = (const float*)d_in[4];  // [P,4H]
    const float* wfc = (const float*)d_in[5];  // [P,O,H]
    const float* bfc = (const float*)d_in[6];  // [P,O]
    float* out = (float*)d_out;                // [B,O,P]

    cudaFuncSetAttribute(k_lstm, cudaFuncAttributeMaxDynamicSharedMemorySize, 196608);

    // transpose+duplicate W_hh (exact grid: P*H*G threads)
    k_transpose<<<(P_ * H_ * G_) / TDIM, TDIM>>>(whh);
    // one CTA per point
    k_lstm<<<P_, BDIM, 196608>>>(x, wih, bih, bhh, wfc, bfc, out);
}

// round 16
// speedup vs baseline: 1.4664x; 1.2513x over previous
#include <cuda_runtime.h>
#include <cstdint>
#include <cstddef>

// ---------------------------------------------------------------------------
// Problem constants
// ---------------------------------------------------------------------------
#define TDIM 512            // transpose kernel block
#define BDIM 128            // lstm kernel block (4 warps), 2 CTAs/SM
constexpr int B_ = 64;    // batch
constexpr int T_ = 96;    // seq len
constexpr int P_ = 256;   // points
constexpr int H_ = 128;   // hidden
constexpr int G_ = 512;   // 4*H gates
constexpr int O_ = 24;    // pred_len
constexpr int KC = 8;             // k-rows per streamed chunk
constexpr int NCH = H_ / KC;      // 16 chunks per timestep
constexpr int CH_BYTES = KC * G_ * 4;   // 16384 B per chunk (undup)
constexpr int HS = 36;            // padded h_s row stride in floats (144B, 16B-mult)

// 64 MB scratch: W_hh transposed to [p][k][g], UNduplicated.
__device__ float g_wt[(size_t)P_ * H_ * G_];

// ---------------------------------------------------------------------------
// PTX helpers
// ---------------------------------------------------------------------------
__device__ __forceinline__ unsigned long long fma2(unsigned long long a,
                                                   unsigned long long b,
                                                   unsigned long long c) {
    unsigned long long d;
    asm("fma.rn.f32x2 %0, %1, %2, %3;" : "=l"(d) : "l"(a), "l"(b), "l"(c));
    return d;
}
__device__ __forceinline__ void lds_v2u64(unsigned addr, unsigned long long& a,
                                          unsigned long long& b) {
    asm volatile("ld.shared.v2.u64 {%0, %1}, [%2];" : "=l"(a), "=l"(b) : "r"(addr));
}
__device__ __forceinline__ float lds_f32(unsigned addr) {
    float v;
    asm volatile("ld.shared.f32 %0, [%1];" : "=f"(v) : "r"(addr));
    return v;
}
__device__ __forceinline__ unsigned long long dup2(float v) {
    unsigned long long d;
    asm("mov.b64 %0, {%1, %1};" : "=l"(d) : "f"(v));
    return d;
}
__device__ __forceinline__ void cp16(unsigned dst, const void* src) {
    asm volatile("cp.async.cg.shared.global [%0], [%1], 16;"
                 :: "r"(dst), "l"(src) : "memory");
}
__device__ __forceinline__ void cp_commit() {
    asm volatile("cp.async.commit_group;" ::: "memory");
}
__device__ __forceinline__ void cp_wait2() {
    asm volatile("cp.async.wait_group 2;" ::: "memory");
}
__device__ __forceinline__ float ftanh(float x) {
    float y;
    asm("tanh.approx.f32 %0, %1;" : "=f"(y) : "f"(x));
    return y;
}
__device__ __forceinline__ float fsig(float x) {
    // sigmoid(x) = 0.5*tanh(0.5x) + 0.5  (single MUFU)
    return fmaf(0.5f, ftanh(0.5f * x), 0.5f);
}
__device__ __forceinline__ float2 unpk(unsigned long long v) {
    float2 r;
    asm("mov.b64 {%0, %1}, %2;" : "=f"(r.x), "=f"(r.y) : "l"(v));
    return r;
}

// ---------------------------------------------------------------------------
// Prep kernel: g_wt[p][k][g] = W_hh[p][g][k]  (undup; coalesced writes)
// ---------------------------------------------------------------------------
__global__ void k_transpose(const float* __restrict__ whh) {
    unsigned idx = blockIdx.x * TDIM + threadIdx.x;  // exact grid: P*H*G threads
    unsigned g  = idx & (G_ - 1);
    unsigned pk = idx >> 9;
    unsigned k  = pk & (H_ - 1);
    unsigned p  = pk >> 7;
    g_wt[idx] = __ldg(&whh[((size_t)p * G_ + g) * H_ + k]);
}

// ---------------------------------------------------------------------------
// Main kernel: grid = 512 = (point, batch-half), 128 threads, 2 CTAs/SM.
// tid = tg*2 + tb; tg in [0,64) -> hidden units (2tg, 2tg+1) over all 4 gate
// classes; tb in [0,2) -> 16 batches (8 b-pairs) at local offset tb*16.
// Per thread: acc[4 gates][2 units][8 b-pairs] as f32x2; c state in regs.
// Weights streamed undup L2 -> smem, 4 x 16KB ring, depth-3 prefetch,
// ONE __syncthreads per chunk. (w,w) operand built in ALU via mov.b64{v,v}.
// ---------------------------------------------------------------------------
__global__ void __launch_bounds__(BDIM, 2) k_lstm(
    const float* __restrict__ x,
    const float* __restrict__ wih,
    const float* __restrict__ bih,
    const float* __restrict__ bhh,
    const float* __restrict__ wfc,
    const float* __restrict__ bfc,
    float* __restrict__ out)
{
    extern __shared__ float sm[];
    // float offsets:
    //   h_s   [128][HS=36]     : 0     .. 4607   (padded rows vs store conflicts)
    //   x_s   [96][32]         : 4608  .. 7679
    //   wih_d [512][2] (dup)   : 7680  .. 8703
    //   bs_d  [512][2] (dup)   : 8704  .. 9727
    //   wbuf  [4][8][512]      : 9728  .. 26111   (4 x 16KB undup ring)
    float* h_s   = sm;
    float* x_s   = sm + 4608;
    float* wih_d = sm + 7680;
    float* bs_d  = sm + 8704;

    const int p    = blockIdx.x >> 1;
    const int boff = (blockIdx.x & 1) * 32;   // global batch offset of this CTA
    const int tid  = threadIdx.x;
    const int tg   = tid >> 1;   // 0..63
    const int tb   = tid & 1;    // 0..1

    // --- init smem -------------------------------------------------------
    for (int i = tid; i < H_ * HS; i += BDIM) h_s[i] = 0.0f;       // h0 = 0
    for (int i = tid; i < T_ * 32; i += BDIM) {
        int t = i >> 5, bl = i & 31;
        x_s[i] = x[((size_t)(boff + bl) * T_ + t) * P_ + p];       // x[b,t,p,0]
    }
    for (int i = tid; i < G_; i += BDIM) {
        float w = wih[(size_t)p * G_ + i];                         // W_ih[p,g,0]
        wih_d[2 * i] = w;  wih_d[2 * i + 1] = w;
        float bs = bih[(size_t)p * G_ + i] + bhh[(size_t)p * G_ + i];
        bs_d[2 * i] = bs;  bs_d[2 * i + 1] = bs;
    }

    const unsigned sbase    = (unsigned)__cvta_generic_to_shared(sm);
    const unsigned h_base   = sbase;
    const unsigned x_base   = sbase + 4608u * 4u;
    const unsigned wih_base = sbase + 7680u * 4u;
    const unsigned bs_base  = sbase + 8704u * 4u;
    const unsigned wb_base  = sbase + 9728u * 4u;

    const float* wsrc = g_wt + (size_t)p * (H_ * G_);  // 65536 floats (undup)

    // --- prologue: prefetch chunks 0,1,2 into bufs 0,1,2 -----------------
#pragma unroll
    for (int c0 = 0; c0 < 3; ++c0) {
        const char* src = (const char*)wsrc + (size_t)c0 * CH_BYTES;
        unsigned dst = wb_base + (unsigned)c0 * (unsigned)CH_BYTES;
#pragma unroll
        for (int n = 0; n < 8; ++n)
            cp16(dst + (unsigned)(tid + n * BDIM) * 16u, src + (size_t)(tid + n * BDIM) * 16);
        cp_commit();
    }
    __syncthreads();   // h_s / x_s / wih_d / bs_d visible

    float2 cst[2][8];
#pragma unroll
    for (int u = 0; u < 2; ++u)
#pragma unroll
        for (int j = 0; j < 8; ++j) cst[u][j] = make_float2(0.0f, 0.0f);

    // --- time loop --------------------------------------------------------
    for (int t = 0; t < T_; ++t) {
        // acc init: gate = x[b]*W_ih[g] + (b_ih+b_hh)[g]
        unsigned long long acc[4][2][8];
        unsigned long long xp[8];
#pragma unroll
        for (int j = 0; j < 4; ++j)
            lds_v2u64(x_base + (unsigned)(t * 32 + tb * 16 + 4 * j) * 4u,
                      xp[2 * j], xp[2 * j + 1]);
#pragma unroll
        for (int c = 0; c < 4; ++c) {
            unsigned long long wd0, wd1, bd0, bd1;
            lds_v2u64(wih_base + (unsigned)(c * 128 + 2 * tg) * 8u, wd0, wd1);
            lds_v2u64(bs_base + (unsigned)(c * 128 + 2 * tg) * 8u, bd0, bd1);
#pragma unroll
            for (int j = 0; j < 8; ++j) {
                acc[c][0][j] = fma2(xp[j], wd0, bd0);
                acc[c][1][j] = fma2(xp[j], wd1, bd1);
            }
        }

        // k loop: gates += h @ W_hh^T, 16 chunks of 8 k's, 4-buffer ring.
        for (int ch = 0; ch < NCH; ++ch) {
            cp_wait2();          // chunk `ch` resident in buf[ch&3]
            __syncthreads();     // publishes cp data + h_s; also: all reads of
                                 // chunk ch-1 (= target of this prefetch) done

            // prefetch chunk (ch+3) & 15 into buf[(ch+3)&3] (read 1 chunk ago)
            {
                int nc = (ch + 3) & 15;
                const char* src = (const char*)wsrc + (size_t)nc * CH_BYTES;
                unsigned dst = wb_base + (unsigned)((ch + 3) & 3) * (unsigned)CH_BYTES;
#pragma unroll
                for (int n = 0; n < 8; ++n)
                    cp16(dst + (unsigned)(tid + n * BDIM) * 16u,
                         src + (size_t)(tid + n * BDIM) * 16);
                cp_commit();
            }

            const unsigned bufb = wb_base + (unsigned)(ch & 3) * (unsigned)CH_BYTES;
            const unsigned hcb  = h_base + (unsigned)(ch * KC * HS + tb * 16) * 4u;
#pragma unroll
            for (int kk = 0; kk < KC; ++kk) {
                unsigned long long hp[8];
                unsigned hk = hcb + (unsigned)kk * (HS * 4u);
                lds_v2u64(hk,       hp[0], hp[1]);
                lds_v2u64(hk + 16u, hp[2], hp[3]);
                lds_v2u64(hk + 32u, hp[4], hp[5]);
                lds_v2u64(hk + 48u, hp[6], hp[7]);
#pragma unroll
                for (int c = 0; c < 4; ++c) {
                    unsigned wa = bufb + (unsigned)(kk * 2048 + (c * 128 + 2 * tg) * 4);
                    unsigned long long w0 = dup2(lds_f32(wa));
                    unsigned long long w1 = dup2(lds_f32(wa + 4u));
                    acc[c][0][0] = fma2(hp[0], w0, acc[c][0][0]);
                    acc[c][0][1] = fma2(hp[1], w0, acc[c][0][1]);
                    acc[c][0][2] = fma2(hp[2], w0, acc[c][0][2]);
                    acc[c][0][3] = fma2(hp[3], w0, acc[c][0][3]);
                    acc[c][0][4] = fma2(hp[4], w0, acc[c][0][4]);
                    acc[c][0][5] = fma2(hp[5], w0, acc[c][0][5]);
                    acc[c][0][6] = fma2(hp[6], w0, acc[c][0][6]);
                    acc[c][0][7] = fma2(hp[7], w0, acc[c][0][7]);
                    acc[c][1][0] = fma2(hp[0], w1, acc[c][1][0]);
                    acc[c][1][1] = fma2(hp[1], w1, acc[c][1][1]);
                    acc[c][1][2] = fma2(hp[2], w1, acc[c][1][2]);
                    acc[c][1][3] = fma2(hp[3], w1, acc[c][1][3]);
                    acc[c][1][4] = fma2(hp[4], w1, acc[c][1][4]);
                    acc[c][1][5] = fma2(hp[5], w1, acc[c][1][5]);
                    acc[c][1][6] = fma2(hp[6], w1, acc[c][1][6]);
                    acc[c][1][7] = fma2(hp[7], w1, acc[c][1][7]);
                }
            }
            // no trailing sync: next iteration's wait+sync provides it
        }

        // epilogue: torch gate order i,f,g,o; c = f*c + i*tanh(g); h = o*tanh(c)
#pragma unroll
        for (int u = 0; u < 2; ++u) {
            int hrow = 2 * tg + u;
#pragma unroll
            for (int j = 0; j < 8; ++j) {
                float2 iv = unpk(acc[0][u][j]);
                float2 fv = unpk(acc[1][u][j]);
                float2 gv = unpk(acc[2][u][j]);
                float2 ov = unpk(acc[3][u][j]);
                float c0 = fsig(fv.x) * cst[u][j].x + fsig(iv.x) * ftanh(gv.x);
                float c1 = fsig(fv.y) * cst[u][j].y + fsig(iv.y) * ftanh(gv.y);
                cst[u][j] = make_float2(c0, c1);
                float h0 = fsig(ov.x) * ftanh(c0);
                float h1 = fsig(ov.y) * ftanh(c1);
                *reinterpret_cast<float2*>(&h_s[hrow * HS + tb * 16 + 2 * j]) =
                    make_float2(h0, h1);
            }
        }
        // next timestep's chunk-0 wait+sync orders these h_s writes before reads
    }
    __syncthreads();   // final h_s visible to all for the FC

    // --- final FC: out[b, o, p] = h[b,:] . W_fc[p,o,:] + b_fc[p,o] -------
#pragma unroll
    for (int r = 0; r < 6; ++r) {
        int idx = tid + r * BDIM;       // 0..767 == 32*24
        int bl = idx / 24;
        int o  = idx - bl * 24;
        const float4* wf = reinterpret_cast<const float4*>(wfc + ((size_t)p * O_ + o) * H_);
        float acc = bfc[(size_t)p * O_ + o];
#pragma unroll
        for (int k4 = 0; k4 < 32; ++k4) {
            float4 w = wf[k4];
            int k = k4 * 4;
            acc += h_s[k * HS + bl] * w.x;
            acc += h_s[(k + 1) * HS + bl] * w.y;
            acc += h_s[(k + 2) * HS + bl] * w.z;
            acc += h_s[(k + 3) * HS + bl] * w.w;
        }
        out[((size_t)(boff + bl) * O_ + o) * P_ + p] = acc;
    }
}

// ---------------------------------------------------------------------------
// Launch
// ---------------------------------------------------------------------------
extern "C" void kernel_launch(void* const* d_in, const int* in_sizes, int n_in,
                              void* d_out, int out_size) {
    (void)in_sizes; (void)n_in; (void)out_size;
    const float* x   = (const float*)d_in[0];  // [B,T,P,1]
    const float* wih = (const float*)d_in[1];  // [P,4H,1]
    const float* whh = (const float*)d_in[2];  // [P,4H,H]
    const float* bih = (const float*)d_in[3];  // [P,4H]
    const float* bhh = (const float*)d_in[4];  // [P,4H]
    const float* wfc = (const float*)d_in[5];  // [P,O,H]
    const float* bfc = (const float*)d_in[6];  // [P,O]
    float* out = (float*)d_out;                // [B,O,P]

    constexpr int SMEM_BYTES = (9728 + 4 * KC * G_) * 4;   // 104448 B
    cudaFuncSetAttribute(k_lstm, cudaFuncAttributeMaxDynamicSharedMemorySize, SMEM_BYTES);

    // transpose W_hh (undup; exact grid: P*H*G threads)
    k_transpose<<<(P_ * H_ * G_) / TDIM, TDIM>>>(whh);
    // 2 CTAs per point (batch halves), 2 CTAs/SM
    k_lstm<<<P_ * 2, BDIM, SMEM_BYTES>>>(x, wih, bih, bhh, wfc, bfc, out);
}

// round 17
// speedup vs baseline: 1.4666x; 1.0002x over previous
#include <cuda_runtime.h>
#include <cstdint>
#include <cstddef>

// ---------------------------------------------------------------------------
// Problem constants
// ---------------------------------------------------------------------------
#define TDIM 512            // transpose kernel block
#define BDIM 128            // lstm kernel block (4 warps), 2 CTAs/SM
constexpr int B_ = 64;    // batch
constexpr int T_ = 96;    // seq len
constexpr int P_ = 256;   // points
constexpr int H_ = 128;   // hidden
constexpr int G_ = 512;   // 4*H gates
constexpr int O_ = 24;    // pred_len
constexpr int KC = 8;             // k-rows per streamed chunk
constexpr int NCH = H_ / KC;      // 16 chunks per timestep
constexpr int CH_BYTES = KC * G_ * 4;   // 16384 B per chunk (undup)
constexpr int HS = 36;            // padded h_s row stride in floats (144B, 16B-mult)

// 64 MB scratch: W_hh transposed to [p][k][g], UNduplicated.
__device__ float g_wt[(size_t)P_ * H_ * G_];

// ---------------------------------------------------------------------------
// PTX helpers
// ---------------------------------------------------------------------------
__device__ __forceinline__ unsigned long long fma2(unsigned long long a,
                                                   unsigned long long b,
                                                   unsigned long long c) {
    unsigned long long d;
    asm("fma.rn.f32x2 %0, %1, %2, %3;" : "=l"(d) : "l"(a), "l"(b), "l"(c));
    return d;
}
__device__ __forceinline__ void lds_v2u64(unsigned addr, unsigned long long& a,
                                          unsigned long long& b) {
    asm volatile("ld.shared.v2.u64 {%0, %1}, [%2];" : "=l"(a), "=l"(b) : "r"(addr));
}
__device__ __forceinline__ float lds_f32(unsigned addr) {
    float v;
    asm volatile("ld.shared.f32 %0, [%1];" : "=f"(v) : "r"(addr));
    return v;
}
__device__ __forceinline__ unsigned long long dup2(float v) {
    unsigned long long d;
    asm("mov.b64 %0, {%1, %1};" : "=l"(d) : "f"(v));
    return d;
}
__device__ __forceinline__ void cp16(unsigned dst, const void* src) {
    asm volatile("cp.async.cg.shared.global [%0], [%1], 16;"
                 :: "r"(dst), "l"(src) : "memory");
}
__device__ __forceinline__ void cp_commit() {
    asm volatile("cp.async.commit_group;" ::: "memory");
}
__device__ __forceinline__ void cp_wait2() {
    asm volatile("cp.async.wait_group 2;" ::: "memory");
}
__device__ __forceinline__ float ftanh(float x) {
    float y;
    asm("tanh.approx.f32 %0, %1;" : "=f"(y) : "f"(x));
    return y;
}
__device__ __forceinline__ float fsig(float x) {
    // sigmoid(x) = 0.5*tanh(0.5x) + 0.5  (single MUFU)
    return fmaf(0.5f, ftanh(0.5f * x), 0.5f);
}
__device__ __forceinline__ float2 unpk(unsigned long long v) {
    float2 r;
    asm("mov.b64 {%0, %1}, %2;" : "=f"(r.x), "=f"(r.y) : "l"(v));
    return r;
}

// ---------------------------------------------------------------------------
// Prep kernel: g_wt[p][k][g] = W_hh[p][g][k]  (undup; coalesced writes)
// ---------------------------------------------------------------------------
__global__ void k_transpose(const float* __restrict__ whh) {
    unsigned idx = blockIdx.x * TDIM + threadIdx.x;  // exact grid: P*H*G threads
    unsigned g  = idx & (G_ - 1);
    unsigned pk = idx >> 9;
    unsigned k  = pk & (H_ - 1);
    unsigned p  = pk >> 7;
    g_wt[idx] = __ldg(&whh[((size_t)p * G_ + g) * H_ + k]);
}

// ---------------------------------------------------------------------------
// Main kernel: grid = 512 = (point, batch-half), 128 threads, 2 CTAs/SM.
// tid = tg*2 + tb; tg in [0,64) -> hidden units (2tg, 2tg+1) over all 4 gate
// classes; tb in [0,2) -> 16 batches (8 b-pairs) at local offset tb*16.
// Per thread: acc[4 gates][2 units][8 b-pairs] as f32x2; c state in regs.
// Weights streamed undup L2 -> smem, 4 x 16KB ring, depth-3 prefetch,
// ONE __syncthreads per chunk. (w,w) operand built in ALU via mov.b64{v,v}.
// ---------------------------------------------------------------------------
__global__ void __launch_bounds__(BDIM, 2) k_lstm(
    const float* __restrict__ x,
    const float* __restrict__ wih,
    const float* __restrict__ bih,
    const float* __restrict__ bhh,
    const float* __restrict__ wfc,
    const float* __restrict__ bfc,
    float* __restrict__ out)
{
    extern __shared__ float sm[];
    // float offsets:
    //   h_s   [128][HS=36]     : 0     .. 4607   (padded rows vs store conflicts)
    //   x_s   [96][32]         : 4608  .. 7679
    //   wih_d [512][2] (dup)   : 7680  .. 8703
    //   bs_d  [512][2] (dup)   : 8704  .. 9727
    //   wbuf  [4][8][512]      : 9728  .. 26111   (4 x 16KB undup ring)
    float* h_s   = sm;
    float* x_s   = sm + 4608;
    float* wih_d = sm + 7680;
    float* bs_d  = sm + 8704;

    const int p    = blockIdx.x >> 1;
    const int boff = (blockIdx.x & 1) * 32;   // global batch offset of this CTA
    const int tid  = threadIdx.x;
    const int tg   = tid >> 1;   // 0..63
    const int tb   = tid & 1;    // 0..1

    // --- init smem -------------------------------------------------------
    for (int i = tid; i < H_ * HS; i += BDIM) h_s[i] = 0.0f;       // h0 = 0
    for (int i = tid; i < T_ * 32; i += BDIM) {
        int t = i >> 5, bl = i & 31;
        x_s[i] = x[((size_t)(boff + bl) * T_ + t) * P_ + p];       // x[b,t,p,0]
    }
    for (int i = tid; i < G_; i += BDIM) {
        float w = wih[(size_t)p * G_ + i];                         // W_ih[p,g,0]
        wih_d[2 * i] = w;  wih_d[2 * i + 1] = w;
        float bs = bih[(size_t)p * G_ + i] + bhh[(size_t)p * G_ + i];
        bs_d[2 * i] = bs;  bs_d[2 * i + 1] = bs;
    }

    const unsigned sbase    = (unsigned)__cvta_generic_to_shared(sm);
    const unsigned h_base   = sbase;
    const unsigned x_base   = sbase + 4608u * 4u;
    const unsigned wih_base = sbase + 7680u * 4u;
    const unsigned bs_base  = sbase + 8704u * 4u;
    const unsigned wb_base  = sbase + 9728u * 4u;

    const float* wsrc = g_wt + (size_t)p * (H_ * G_);  // 65536 floats (undup)

    // --- prologue: prefetch chunks 0,1,2 into bufs 0,1,2 -----------------
#pragma unroll
    for (int c0 = 0; c0 < 3; ++c0) {
        const char* src = (const char*)wsrc + (size_t)c0 * CH_BYTES;
        unsigned dst = wb_base + (unsigned)c0 * (unsigned)CH_BYTES;
#pragma unroll
        for (int n = 0; n < 8; ++n)
            cp16(dst + (unsigned)(tid + n * BDIM) * 16u, src + (size_t)(tid + n * BDIM) * 16);
        cp_commit();
    }
    __syncthreads();   // h_s / x_s / wih_d / bs_d visible

    float2 cst[2][8];
#pragma unroll
    for (int u = 0; u < 2; ++u)
#pragma unroll
        for (int j = 0; j < 8; ++j) cst[u][j] = make_float2(0.0f, 0.0f);

    // --- time loop --------------------------------------------------------
    for (int t = 0; t < T_; ++t) {
        // acc init: gate = x[b]*W_ih[g] + (b_ih+b_hh)[g]
        unsigned long long acc[4][2][8];
        unsigned long long xp[8];
#pragma unroll
        for (int j = 0; j < 4; ++j)
            lds_v2u64(x_base + (unsigned)(t * 32 + tb * 16 + 4 * j) * 4u,
                      xp[2 * j], xp[2 * j + 1]);
#pragma unroll
        for (int c = 0; c < 4; ++c) {
            unsigned long long wd0, wd1, bd0, bd1;
            lds_v2u64(wih_base + (unsigned)(c * 128 + 2 * tg) * 8u, wd0, wd1);
            lds_v2u64(bs_base + (unsigned)(c * 128 + 2 * tg) * 8u, bd0, bd1);
#pragma unroll
            for (int j = 0; j < 8; ++j) {
                acc[c][0][j] = fma2(xp[j], wd0, bd0);
                acc[c][1][j] = fma2(xp[j], wd1, bd1);
            }
        }

        // k loop: gates += h @ W_hh^T, 16 chunks of 8 k's, 4-buffer ring.
        for (int ch = 0; ch < NCH; ++ch) {
            cp_wait2();          // chunk `ch` resident in buf[ch&3]
            __syncthreads();     // publishes cp data + h_s; also: all reads of
                                 // chunk ch-1 (= target of this prefetch) done

            // prefetch chunk (ch+3) & 15 into buf[(ch+3)&3] (read 1 chunk ago)
            {
                int nc = (ch + 3) & 15;
                const char* src = (const char*)wsrc + (size_t)nc * CH_BYTES;
                unsigned dst = wb_base + (unsigned)((ch + 3) & 3) * (unsigned)CH_BYTES;
#pragma unroll
                for (int n = 0; n < 8; ++n)
                    cp16(dst + (unsigned)(tid + n * BDIM) * 16u,
                         src + (size_t)(tid + n * BDIM) * 16);
                cp_commit();
            }

            const unsigned bufb = wb_base + (unsigned)(ch & 3) * (unsigned)CH_BYTES;
            const unsigned hcb  = h_base + (unsigned)(ch * KC * HS + tb * 16) * 4u;
#pragma unroll
            for (int kk = 0; kk < KC; ++kk) {
                unsigned long long hp[8];
                unsigned hk = hcb + (unsigned)kk * (HS * 4u);
                lds_v2u64(hk,       hp[0], hp[1]);
                lds_v2u64(hk + 16u, hp[2], hp[3]);
                lds_v2u64(hk + 32u, hp[4], hp[5]);
                lds_v2u64(hk + 48u, hp[6], hp[7]);
#pragma unroll
                for (int c = 0; c < 4; ++c) {
                    unsigned wa = bufb + (unsigned)(kk * 2048 + (c * 128 + 2 * tg) * 4);
                    unsigned long long w0 = dup2(lds_f32(wa));
                    unsigned long long w1 = dup2(lds_f32(wa + 4u));
                    acc[c][0][0] = fma2(hp[0], w0, acc[c][0][0]);
                    acc[c][0][1] = fma2(hp[1], w0, acc[c][0][1]);
                    acc[c][0][2] = fma2(hp[2], w0, acc[c][0][2]);
                    acc[c][0][3] = fma2(hp[3], w0, acc[c][0][3]);
                    acc[c][0][4] = fma2(hp[4], w0, acc[c][0][4]);
                    acc[c][0][5] = fma2(hp[5], w0, acc[c][0][5]);
                    acc[c][0][6] = fma2(hp[6], w0, acc[c][0][6]);
                    acc[c][0][7] = fma2(hp[7], w0, acc[c][0][7]);
                    acc[c][1][0] = fma2(hp[0], w1, acc[c][1][0]);
                    acc[c][1][1] = fma2(hp[1], w1, acc[c][1][1]);
                    acc[c][1][2] = fma2(hp[2], w1, acc[c][1][2]);
                    acc[c][1][3] = fma2(hp[3], w1, acc[c][1][3]);
                    acc[c][1][4] = fma2(hp[4], w1, acc[c][1][4]);
                    acc[c][1][5] = fma2(hp[5], w1, acc[c][1][5]);
                    acc[c][1][6] = fma2(hp[6], w1, acc[c][1][6]);
                    acc[c][1][7] = fma2(hp[7], w1, acc[c][1][7]);
                }
            }
            // no trailing sync: next iteration's wait+sync provides it
        }

        // epilogue: torch gate order i,f,g,o; c = f*c + i*tanh(g); h = o*tanh(c)
#pragma unroll
        for (int u = 0; u < 2; ++u) {
            int hrow = 2 * tg + u;
#pragma unroll
            for (int j = 0; j < 8; ++j) {
                float2 iv = unpk(acc[0][u][j]);
                float2 fv = unpk(acc[1][u][j]);
                float2 gv = unpk(acc[2][u][j]);
                float2 ov = unpk(acc[3][u][j]);
                float c0 = fsig(fv.x) * cst[u][j].x + fsig(iv.x) * ftanh(gv.x);
                float c1 = fsig(fv.y) * cst[u][j].y + fsig(iv.y) * ftanh(gv.y);
                cst[u][j] = make_float2(c0, c1);
                float h0 = fsig(ov.x) * ftanh(c0);
                float h1 = fsig(ov.y) * ftanh(c1);
                *reinterpret_cast<float2*>(&h_s[hrow * HS + tb * 16 + 2 * j]) =
                    make_float2(h0, h1);
            }
        }
        // next timestep's chunk-0 wait+sync orders these h_s writes before reads
    }
    __syncthreads();   // final h_s visible to all for the FC

    // --- final FC: out[b, o, p] = h[b,:] . W_fc[p,o,:] + b_fc[p,o] -------
#pragma unroll
    for (int r = 0; r < 6; ++r) {
        int idx = tid + r * BDIM;       // 0..767 == 32*24
        int bl = idx / 24;
        int o  = idx - bl * 24;
        const float4* wf = reinterpret_cast<const float4*>(wfc + ((size_t)p * O_ + o) * H_);
        float acc = bfc[(size_t)p * O_ + o];
#pragma unroll
        for (int k4 = 0; k4 < 32; ++k4) {
            float4 w = wf[k4];
            int k = k4 * 4;
            acc += h_s[k * HS + bl] * w.x;
            acc += h_s[(k + 1) * HS + bl] * w.y;
            acc += h_s[(k + 2) * HS + bl] * w.z;
            acc += h_s[(k + 3) * HS + bl] * w.w;
        }
        out[((size_t)(boff + bl) * O_ + o) * P_ + p] = acc;
    }
}

// ---------------------------------------------------------------------------
// Launch
// ---------------------------------------------------------------------------
extern "C" void kernel_launch(void* const* d_in, const int* in_sizes, int n_in,
                              void* d_out, int out_size) {
    (void)in_sizes; (void)n_in; (void)out_size;
    const float* x   = (const float*)d_in[0];  // [B,T,P,1]
    const float* wih = (const float*)d_in[1];  // [P,4H,1]
    const float* whh = (const float*)d_in[2];  // [P,4H,H]
    const float* bih = (const float*)d_in[3];  // [P,4H]
    const float* bhh = (const float*)d_in[4];  // [P,4H]
    const float* wfc = (const float*)d_in[5];  // [P,O,H]
    const float* bfc = (const float*)d_in[6];  // [P,O]
    float* out = (float*)d_out;                // [B,O,P]

    constexpr int SMEM_BYTES = (9728 + 4 * KC * G_) * 4;   // 104448 B
    cudaFuncSetAttribute(k_lstm, cudaFuncAttributeMaxDynamicSharedMemorySize, SMEM_BYTES);

    // transpose W_hh (undup; exact grid: P*H*G threads)
    k_transpose<<<(P_ * H_ * G_) / TDIM, TDIM>>>(whh);
    // 2 CTAs per point (batch halves), 2 CTAs/SM
    k_lstm<<<P_ * 2, BDIM, SMEM_BYTES>>>(x, wih, bih, bhh, wfc, bfc, out);
}